// round 1
// baseline (speedup 1.0000x reference)
#include <cuda_runtime.h>

#define C_IN   64
#define C_OUT  64
#define Hdim   224
#define Wdim   224
#define KVOL   576            // C_IN * 3 * 3 elements per output-channel filter
#define WT     112            // w-tile per CTA
#define CIC    8              // ci chunk size

// Ternarized, alpha-scaled weights, laid out [flat(ci,kh,kw)][co] so that
// co is the fastest dim (enables LDS.64 loads of co-pairs for f32x2 FMA).
__device__ float g_tw[KVOL * C_OUT];

// ---------------- packed f32x2 helpers (sm_100+ only) ----------------
__device__ __forceinline__ unsigned long long pack2(float lo, float hi) {
    unsigned long long r;
    asm("mov.b64 %0, {%1, %2};" : "=l"(r) : "f"(lo), "f"(hi));
    return r;
}
__device__ __forceinline__ void unpack2(unsigned long long v, float& lo, float& hi) {
    asm("mov.b64 {%0, %1}, %2;" : "=f"(lo), "=f"(hi) : "l"(v));
}
__device__ __forceinline__ void fma2(unsigned long long& d, unsigned long long a,
                                     unsigned long long b) {
    asm("fma.rn.f32x2 %0, %1, %2, %0;" : "+l"(d) : "l"(a), "l"(b));
}

// ---------------- ternarize: one block per output channel ----------------
__global__ void ternarize_kernel(const float* __restrict__ weight) {
    __shared__ float red[256];
    __shared__ float red2[256];
    __shared__ float s_delta, s_alpha;

    const int co  = blockIdx.x;
    const int tid = threadIdx.x;
    const float* w = weight + co * KVOL;

    float v0 = (tid       < KVOL) ? w[tid]       : 0.0f;
    float v1 = (tid + 256 < KVOL) ? w[tid + 256] : 0.0f;
    float v2 = (tid + 512 < KVOL) ? w[tid + 512] : 0.0f;
    float a0 = fabsf(v0), a1 = fabsf(v1), a2 = fabsf(v2);

    red[tid] = a0 + a1 + a2;
    __syncthreads();
    for (int s = 128; s > 0; s >>= 1) {
        if (tid < s) red[tid] += red[tid + s];
        __syncthreads();
    }
    if (tid == 0) s_delta = (float)(0.7 / 576.0) * red[0];
    __syncthreads();
    const float delta = s_delta;

    // masked sum and count (mask = |w| > delta); padding values are 0 -> never > delta
    float m0 = (a0 > delta) ? 1.0f : 0.0f;
    float m1 = (a1 > delta) ? 1.0f : 0.0f;
    float m2 = (a2 > delta) ? 1.0f : 0.0f;
    red[tid]  = m0 * a0 + m1 * a1 + m2 * a2;
    red2[tid] = m0 + m1 + m2;
    __syncthreads();
    for (int s = 128; s > 0; s >>= 1) {
        if (tid < s) { red[tid] += red[tid + s]; red2[tid] += red2[tid + s]; }
        __syncthreads();
    }
    if (tid == 0) {
        float cnt = red2[0];
        if (cnt < 0.5f) cnt = 1.0f;
        float al = red[0] / cnt;
        s_alpha = fmaxf(al, 1e-4f);
    }
    __syncthreads();
    const float alpha = s_alpha;

    if (tid < KVOL) {
        float t = (v0 > delta) ? 1.0f : ((v0 < -delta) ? -1.0f : 0.0f);
        g_tw[tid * C_OUT + co] = t * alpha;
    }
    if (tid + 256 < KVOL) {
        float t = (v1 > delta) ? 1.0f : ((v1 < -delta) ? -1.0f : 0.0f);
        g_tw[(tid + 256) * C_OUT + co] = t * alpha;
    }
    if (tid + 512 < KVOL) {
        float t = (v2 > delta) ? 1.0f : ((v2 < -delta) ? -1.0f : 0.0f);
        g_tw[(tid + 512) * C_OUT + co] = t * alpha;
    }
}

// ---------------- conv: CTA = one (n, h) x 112 w x all 64 co ----------------
// threads: 256 = 16 co-groups (4 co each, as two f32x2 pairs) x 16 w-groups (7 w each)
__global__ void __launch_bounds__(256)
conv_kernel(const float* __restrict__ x, const float* __restrict__ bias,
            float* __restrict__ out) {
    __shared__ float s_w[CIC * 9 * C_OUT];        // [ci_l][kh][kw][co]  18 KB
    __shared__ float s_x[CIC][3][WT + 2];         // halo'd x rows       10.9 KB

    const int tid     = threadIdx.x;
    const int w_t     = tid & 15;
    const int co_t    = tid >> 4;
    const int co_base = co_t * 4;
    const int w0      = blockIdx.x * WT;
    const int h       = blockIdx.y;
    const int n       = blockIdx.z;

    unsigned long long accA[7], accB[7];
#pragma unroll
    for (int i = 0; i < 7; i++) { accA[i] = 0ull; accB[i] = 0ull; }

    const float* xbase = x + (size_t)n * C_IN * (Hdim * Wdim);

    for (int cc = 0; cc < C_IN / CIC; cc++) {
        // ---- stage weight chunk: CIC*9*64 = 4608 floats (contiguous in g_tw) ----
        const float* gw = g_tw + cc * (CIC * 9 * C_OUT);
#pragma unroll
        for (int i = 0; i < (CIC * 9 * C_OUT) / 256; i++)
            s_w[tid + i * 256] = gw[tid + i * 256];

        // ---- stage x chunk with zero-padded halo: CIC*3*(WT+2) = 2736 floats ----
        for (int idx = tid; idx < CIC * 3 * (WT + 2); idx += 256) {
            int ci_l = idx / (3 * (WT + 2));
            int r    = idx % (3 * (WT + 2));
            int kh   = r / (WT + 2);
            int j    = r % (WT + 2);
            int row  = h + kh - 1;
            int col  = w0 - 1 + j;
            float v = 0.0f;
            if (row >= 0 && row < Hdim && col >= 0 && col < Wdim)
                v = xbase[(size_t)(cc * CIC + ci_l) * (Hdim * Wdim) + row * Wdim + col];
            s_x[ci_l][kh][j] = v;
        }
        __syncthreads();

        // ---- compute ----
#pragma unroll 1
        for (int ci_l = 0; ci_l < CIC; ci_l++) {
#pragma unroll
            for (int kh = 0; kh < 3; kh++) {
                const float* xr = &s_x[ci_l][kh][w_t * 7];
                unsigned long long px[9];
#pragma unroll
                for (int j = 0; j < 9; j++) {
                    float xv = xr[j];
                    px[j] = pack2(xv, xv);
                }
                const float* wr = s_w + (ci_l * 9 + kh * 3) * C_OUT + co_base;
#pragma unroll
                for (int kw = 0; kw < 3; kw++) {
                    unsigned long long wA =
                        *reinterpret_cast<const unsigned long long*>(wr + kw * C_OUT);
                    unsigned long long wB =
                        *reinterpret_cast<const unsigned long long*>(wr + kw * C_OUT + 2);
#pragma unroll
                    for (int i = 0; i < 7; i++) {
                        fma2(accA[i], wA, px[i + kw]);
                        fma2(accB[i], wB, px[i + kw]);
                    }
                }
            }
        }
        __syncthreads();
    }

    // ---- epilogue: unpack, add bias, store ----
    const float b0 = bias[co_base + 0];
    const float b1 = bias[co_base + 1];
    const float b2 = bias[co_base + 2];
    const float b3 = bias[co_base + 3];
    float* obase = out + ((size_t)(n * C_OUT + co_base)) * (Hdim * Wdim)
                       + h * Wdim + w0 + w_t * 7;
#pragma unroll
    for (int i = 0; i < 7; i++) {
        float r0, r1, r2, r3;
        unpack2(accA[i], r0, r1);
        unpack2(accB[i], r2, r3);
        obase[i]                   = r0 + b0;
        obase[1 * Hdim * Wdim + i] = r1 + b1;
        obase[2 * Hdim * Wdim + i] = r2 + b2;
        obase[3 * Hdim * Wdim + i] = r3 + b3;
    }
}

extern "C" void kernel_launch(void* const* d_in, const int* in_sizes, int n_in,
                              void* d_out, int out_size) {
    const float* x      = (const float*)d_in[0];
    const float* weight = (const float*)d_in[1];
    const float* bias   = (const float*)d_in[2];
    float* out          = (float*)d_out;

    ternarize_kernel<<<C_OUT, 256>>>(weight);

    dim3 grid(Wdim / WT, Hdim, 16);   // (2, 224, 16)
    conv_kernel<<<grid, 256>>>(x, bias, out);
}

// round 3
// speedup vs baseline: 1.9435x; 1.9435x over previous
#include <cuda_runtime.h>
#include <cuda_bf16.h>
#include <cstdint>

#define C_IN   64
#define C_OUT  64
#define Hdim   224
#define Wdim   224
#define HW     (Hdim * Wdim)
#define HC     4                 // h rows per CTA
#define ROWU   136               // u32 stride of one ci-row in x buffer (conflict-free)
#define ROWSZ  (64 * ROWU)       // u32 per staged x row (all ci)
#define WCI    72                // ushort stride of ci in weight smem (conflict-free)
#define WS_BYTES (9 * 64 * WCI * 2)              // 82944
#define X_OFF    WS_BYTES
#define SMEM_TOTAL (X_OFF + 3 * ROWSZ * 4)       // 187392

// ternary pattern {-1,0,+1} as bf16 bits, layout [tap][ci][co]
__device__ unsigned short g_tb[9 * C_IN * C_OUT];
__device__ float g_alpha[C_OUT];

// ---------------------------------------------------------------- ternarize
__global__ void ternarize_kernel(const float* __restrict__ weight) {
    __shared__ float red[256], red2[256];
    __shared__ float s_delta, s_alpha;
    const int co = blockIdx.x, tid = threadIdx.x;
    const float* w = weight + co * 576;

    float v0 = (tid < 576) ? w[tid] : 0.0f;
    float v1 = (tid + 256 < 576) ? w[tid + 256] : 0.0f;
    float v2 = (tid + 512 < 576) ? w[tid + 512] : 0.0f;
    float a0 = fabsf(v0), a1 = fabsf(v1), a2 = fabsf(v2);

    red[tid] = a0 + a1 + a2;
    __syncthreads();
    for (int s = 128; s > 0; s >>= 1) { if (tid < s) red[tid] += red[tid + s]; __syncthreads(); }
    if (tid == 0) s_delta = (float)(0.7 / 576.0) * red[0];
    __syncthreads();
    const float delta = s_delta;

    float m0 = (a0 > delta) ? 1.f : 0.f, m1 = (a1 > delta) ? 1.f : 0.f, m2 = (a2 > delta) ? 1.f : 0.f;
    red[tid] = m0 * a0 + m1 * a1 + m2 * a2;
    red2[tid] = m0 + m1 + m2;
    __syncthreads();
    for (int s = 128; s > 0; s >>= 1) {
        if (tid < s) { red[tid] += red[tid + s]; red2[tid] += red2[tid + s]; }
        __syncthreads();
    }
    if (tid == 0) {
        float cnt = red2[0]; if (cnt < 0.5f) cnt = 1.0f;
        s_alpha = fmaxf(red[0] / cnt, 1e-4f);
        g_alpha[co] = s_alpha;
    }
    __syncthreads();

#pragma unroll
    for (int q = 0; q < 3; q++) {
        int f = tid + q * 256;
        if (f < 576) {
            float v = (q == 0) ? v0 : (q == 1) ? v1 : v2;
            float t = (v > delta) ? 1.0f : ((v < -delta) ? -1.0f : 0.0f);
            int ci = f / 9, tap = f % 9;       // w layout [co][ci][kh][kw]
            g_tb[(tap * C_IN + ci) * C_OUT + co] =
                __bfloat16_as_ushort(__float2bfloat16(t));
        }
    }
}

// ---------------------------------------------------------------- helpers
__device__ __forceinline__ void mma16816(float* c, const uint32_t* a,
                                         uint32_t b0, uint32_t b1) {
    asm volatile(
        "mma.sync.aligned.m16n8k16.row.col.f32.bf16.bf16.f32 "
        "{%0,%1,%2,%3}, {%4,%5,%6,%7}, {%8,%9}, {%0,%1,%2,%3};"
        : "+f"(c[0]), "+f"(c[1]), "+f"(c[2]), "+f"(c[3])
        : "r"(a[0]), "r"(a[1]), "r"(a[2]), "r"(a[3]), "r"(b0), "r"(b1));
}

__device__ __forceinline__ void stage_row(uint32_t* sx, const float* xn,
                                          int row, int slot, int w0, int tid) {
    uint32_t* dst = sx + slot * ROWSZ;
    const bool rok = (unsigned)row < (unsigned)Hdim;
    const float* rp = xn + row * Wdim;
    for (int i = tid; i < C_IN * 130; i += 256) {
        int ci = i / 130;
        int j = i - ci * 130;
        int col = w0 - 1 + j;
        float v = 0.0f;
        if (rok && (unsigned)col < (unsigned)Wdim)
            v = rp[(size_t)ci * HW + col];
        uint32_t hb = __bfloat16_as_ushort(__float2bfloat16(v));
        float hf = __uint_as_float(hb << 16);
        uint32_t lb = __bfloat16_as_ushort(__float2bfloat16(v - hf));
        dst[ci * ROWU + j] = hb | (lb << 16);
    }
}

// ---------------------------------------------------------------- conv
// grid (2, 56, 16): bx -> w0 = 0/96 (32px overlap writes identical values),
// by -> 4-row h chunk, bz -> n. 256 threads = 8 warps in 4(M) x 2(N).
__global__ void __launch_bounds__(256, 1)
conv_kernel(const float* __restrict__ x, const float* __restrict__ bias,
            float* __restrict__ out) {
    extern __shared__ char smem[];
    unsigned short* ws = (unsigned short*)smem;
    uint32_t* sx = (uint32_t*)(smem + X_OFF);

    const int tid = threadIdx.x, lane = tid & 31, wid = tid >> 5;
    const int gr = lane >> 2, tc = lane & 3;
    const int wm = wid & 3, wn = wid >> 2;
    const int w0 = blockIdx.x * 96;
    const int h0 = blockIdx.y * HC;
    const int n  = blockIdx.z;
    const float* xn = x + (size_t)n * C_IN * HW;

    // stage ternary weights -> smem [tap][ci(stride 72)][co]
    {
        const uint32_t* src = (const uint32_t*)g_tb;
        uint32_t* wd = (uint32_t*)ws;
        for (int i = tid; i < 9 * 64 * 32; i += 256) {
            int tci = i >> 5, p = i & 31;
            wd[tci * (WCI / 2) + p] = src[i];
        }
    }

    // per-thread alpha/bias for owned output columns
    float al[4][2], bi[4][2];
#pragma unroll
    for (int nt = 0; nt < 4; nt++) {
        int co = wn * 32 + nt * 8 + 2 * tc;
        al[nt][0] = g_alpha[co];     al[nt][1] = g_alpha[co + 1];
        bi[nt][0] = bias[co];        bi[nt][1] = bias[co + 1];
    }

    stage_row(sx, xn, h0 - 1, h0 % 3, w0, tid);
    stage_row(sx, xn, h0, (h0 + 1) % 3, w0, tid);

    for (int hi_it = 0; hi_it < HC; hi_it++) {
        const int h = h0 + hi_it;
        stage_row(sx, xn, h + 1, (h + 2) % 3, w0, tid);
        __syncthreads();

        float acc[2][4][4];
#pragma unroll
        for (int mt = 0; mt < 2; mt++)
#pragma unroll
            for (int nt = 0; nt < 4; nt++)
#pragma unroll
                for (int e = 0; e < 4; e++) acc[mt][nt][e] = 0.0f;

#pragma unroll 1
        for (int kh = 0; kh < 3; kh++) {
            const uint32_t* rowb = sx + ((h + kh) % 3) * ROWSZ + tc * ROWU + wm * 32 + gr;
#pragma unroll 1
            for (int kw = 0; kw < 3; kw++) {
                const uint32_t* ap0 = rowb + kw;
                const unsigned short* bp0 =
                    ws + (kh * 3 + kw) * (64 * WCI) + tc * WCI + wn * 32 + gr;
#pragma unroll
                for (int ks = 0; ks < 8; ks++) {
                    const uint32_t* ap = ap0 + ks * 8 * ROWU;
                    const unsigned short* bp = bp0 + ks * 8 * WCI;
                    uint32_t ra[2][4];
#pragma unroll
                    for (int mt = 0; mt < 2; mt++) {
                        const uint32_t* a = ap + mt * 16;
                        ra[mt][0] = a[0];
                        ra[mt][1] = a[8];
                        ra[mt][2] = a[4 * ROWU];
                        ra[mt][3] = a[4 * ROWU + 8];
                    }
#pragma unroll
                    for (int nt = 0; nt < 4; nt++) {
                        uint32_t t0 = bp[nt * 8];
                        uint32_t t1 = bp[nt * 8 + 4 * WCI];
                        uint32_t rb0 = __byte_perm(t0, t0, 0x1010);
                        uint32_t rb1 = __byte_perm(t1, t1, 0x1010);
                        mma16816(acc[0][nt], ra[0], rb0, rb1);
                        mma16816(acc[1][nt], ra[1], rb0, rb1);
                    }
                }
            }
        }

        // epilogue: scale by alpha, add bias, store
#pragma unroll
        for (int mt = 0; mt < 2; mt++) {
#pragma unroll
            for (int nt = 0; nt < 4; nt++) {
                int co = wn * 32 + nt * 8 + 2 * tc;
                int wg = w0 + wm * 32 + mt * 16 + gr;
                float* p = out + ((size_t)(n * C_OUT + co)) * HW + h * Wdim + wg;
                p[0]      = acc[mt][nt][0] * al[nt][0] + bi[nt][0];
                p[HW]     = acc[mt][nt][1] * al[nt][1] + bi[nt][1];
                p[8]      = acc[mt][nt][2] * al[nt][0] + bi[nt][0];
                p[HW + 8] = acc[mt][nt][3] * al[nt][1] + bi[nt][1];
            }
        }
        __syncthreads();
    }
}

extern "C" void kernel_launch(void* const* d_in, const int* in_sizes, int n_in,
                              void* d_out, int out_size) {
    const float* x      = (const float*)d_in[0];
    const float* weight = (const float*)d_in[1];
    const float* bias   = (const float*)d_in[2];
    float* out          = (float*)d_out;

    static int attr_set = 0;
    cudaFuncSetAttribute(conv_kernel, cudaFuncAttributeMaxDynamicSharedMemorySize,
                         SMEM_TOTAL);
    (void)attr_set;

    ternarize_kernel<<<C_OUT, 256>>>(weight);

    dim3 grid(2, Hdim / HC, 16);   // (2, 56, 16)
    conv_kernel<<<grid, 256, SMEM_TOTAL>>>(x, bias, out);
}